// round 16
// baseline (speedup 1.0000x reference)
#include <cuda_runtime.h>
#include <cstdint>

#define Bb   64
#define Tt   1024
#define Ee   512
#define Vv   256

typedef unsigned long long u64;

// ---------------- device scratch ----------------
__device__ float    g_P[Vv * Ee];                  // P[v][o] = emb[v]·w_x[o] + b_cell[o]
__device__ float    g_hs[(size_t)Tt * Bb * Ee];    // hs[t][b][e]  (128 MB)
__device__ unsigned g_flag[128 * 8 * 32];          // per-CTA per-chunk flag, 128B stride

// ---------------- packed f32x2 helpers ----------------
__device__ __forceinline__ u64 fma2(u64 a, u64 b, u64 c) {
    u64 d;
    asm("fma.rn.f32x2 %0, %1, %2, %3;" : "=l"(d) : "l"(a), "l"(b), "l"(c));
    return d;
}
__device__ __forceinline__ float lo32(u64 v) { return __uint_as_float((unsigned)(v & 0xffffffffull)); }
__device__ __forceinline__ float hi32(u64 v) { return __uint_as_float((unsigned)(v >> 32)); }
__device__ __forceinline__ float hsum(u64 v) { return lo32(v) + hi32(v); }
__device__ __forceinline__ u64 pack2(float a) {
    u64 d; asm("mov.b64 %0, {%1, %1};" : "=l"(d) : "r"(__float_as_uint(a))); return d;
}
__device__ __forceinline__ void st_rel(unsigned* p, unsigned v) {
    asm volatile("st.release.gpu.global.u32 [%0], %1;" :: "l"(p), "r"(v) : "memory");
}
__device__ __forceinline__ unsigned ld_acq(const unsigned* p) {
    unsigned v;
    asm volatile("ld.acquire.gpu.global.u32 %0, [%1];" : "=r"(v) : "l"(p) : "memory");
    return v;
}

// ---------------- flag reset (each replay) ----------------
__global__ void zero_flag_kernel() {
    int i = blockIdx.x * 256 + threadIdx.x;
    g_flag[i] = 0u;
}

// ---------------- P = emb @ w_x^T + b_cell   (256 x 512, K=512) ----------------
__global__ void p_gemm_kernel(const float* __restrict__ emb,
                              const float* __restrict__ w_cell,
                              const float* __restrict__ b_cell) {
    __shared__ float As[64][16];
    __shared__ float Bs[16][64];
    int tid = threadIdx.x;
    int rbase = blockIdx.x * 64;   // v
    int cbase = blockIdx.y * 64;   // o
    int ti = tid >> 4, tj = tid & 15;
    int arow = tid >> 2, ac4 = (tid & 3) * 4;
    float acc[4][4] = {};

    for (int k0 = 0; k0 < Ee; k0 += 16) {
        float4 av = *(const float4*)&emb[(rbase + arow) * Ee + k0 + ac4];
        *(float4*)&As[arow][ac4] = av;
        float4 bv = *(const float4*)&w_cell[(size_t)(cbase + arow) * (2 * Ee) + k0 + ac4];
        Bs[ac4 + 0][arow] = bv.x; Bs[ac4 + 1][arow] = bv.y;
        Bs[ac4 + 2][arow] = bv.z; Bs[ac4 + 3][arow] = bv.w;
        __syncthreads();
#pragma unroll
        for (int kk = 0; kk < 16; kk++) {
            float a0 = As[ti * 4 + 0][kk];
            float a1 = As[ti * 4 + 1][kk];
            float a2 = As[ti * 4 + 2][kk];
            float a3 = As[ti * 4 + 3][kk];
            float4 b4 = *(const float4*)&Bs[kk][tj * 4];
            acc[0][0] = fmaf(a0, b4.x, acc[0][0]); acc[0][1] = fmaf(a0, b4.y, acc[0][1]);
            acc[0][2] = fmaf(a0, b4.z, acc[0][2]); acc[0][3] = fmaf(a0, b4.w, acc[0][3]);
            acc[1][0] = fmaf(a1, b4.x, acc[1][0]); acc[1][1] = fmaf(a1, b4.y, acc[1][1]);
            acc[1][2] = fmaf(a1, b4.z, acc[1][2]); acc[1][3] = fmaf(a1, b4.w, acc[1][3]);
            acc[2][0] = fmaf(a2, b4.x, acc[2][0]); acc[2][1] = fmaf(a2, b4.y, acc[2][1]);
            acc[2][2] = fmaf(a2, b4.z, acc[2][2]); acc[2][3] = fmaf(a2, b4.w, acc[2][3]);
            acc[3][0] = fmaf(a3, b4.x, acc[3][0]); acc[3][1] = fmaf(a3, b4.y, acc[3][1]);
            acc[3][2] = fmaf(a3, b4.z, acc[3][2]); acc[3][3] = fmaf(a3, b4.w, acc[3][3]);
        }
        __syncthreads();
    }
#pragma unroll
    for (int ii = 0; ii < 4; ii++) {
        int r = rbase + ti * 4 + ii;
        int c = cbase + tj * 4;
        float4 o;
        o.x = acc[ii][0] + b_cell[c + 0];
        o.y = acc[ii][1] + b_cell[c + 1];
        o.z = acc[ii][2] + b_cell[c + 2];
        o.w = acc[ii][3] + b_cell[c + 3];
        *(float4*)&g_P[r * Ee + c] = o;
    }
}

// ---------------- persistent recurrence kernel (R13/R12, proven) ----------------
__global__ void __launch_bounds__(256, 1)
rnn_rec_kernel(const int* __restrict__ x,
               const float* __restrict__ w_cell,
               const float* __restrict__ h0) {
    __shared__ __align__(16) float hsm[8 * 256];     // 8 KB
    __shared__ float psum[2][8 * 288];               // 2 x 9 KB: [p][q*288 + b*72 + c]

    int tid = threadIdx.x;
    int bid = blockIdx.x;
    int io  = bid & 7,  grp = bid >> 3;
    int obase = io * 64, bbase = grp * 4;
    int l  = tid & 31;
    int ks = tid >> 5;
    int k0 = ks * 64;

    // preload w_h for 2 cols
    u64 wA[32], wB[32];
    {
        const u64* wp = (const u64*)w_cell;
        int baseA = ((obase + l)      * (2 * Ee) + Ee + k0) >> 1;
        int baseB = ((obase + l + 32) * (2 * Ee) + Ee + k0) >> 1;
#pragma unroll
        for (int j = 0; j < 32; j++) wA[j] = wp[baseA + j];
#pragma unroll
        for (int j = 0; j < 32; j++) wB[j] = wp[baseB + j];
    }

    unsigned* myflag = &g_flag[(bid * 8 + ks) * 32];
    const unsigned* fA = &g_flag[((grp * 8 + ks) * 8 + ((l & 15) >> 1)) * 32];

    int rb = l >> 3, rc = ks * 8 + (l & 7);
    const int* xrow = x + (bbase + rb) * Tt;
    const float* prow_base = g_P + obase + rc;

    int bq0 = l >> 4, bq1 = (l + 32) >> 4;
    int kk  = (l & 15) * 4;

    float* myhsm = hsm + ks * 256;

    for (int t = 0; t < Tt; t++) {
        int p = t & 1;
        int   xv = __ldg(xrow + t);
        float pv = __ldg(&prow_base[xv * Ee]);

        if (t == 0) {
#pragma unroll
            for (int q = 0; q < 2; q++) {
                int idx = l + 32 * q;
                int kq  = (idx & 15) * 4;
                *(float4*)&myhsm[(idx >> 4) * 64 + kq] = *(const float4*)&h0[k0 + kq];
            }
        } else {
            while (ld_acq(fA) < (unsigned)t) { }
            const float* base = g_hs + ((size_t)(t - 1) * Bb + bbase) * Ee + k0 + kk;
            float4 v0 = __ldcg((const float4*)(base + (size_t)bq0 * Ee));
            float4 v1 = __ldcg((const float4*)(base + (size_t)bq1 * Ee));
            *(float4*)&myhsm[bq0 * 64 + kk] = v0;
            *(float4*)&myhsm[bq1 * 64 + kk] = v1;
        }
        __syncwarp();

        // ---- partial dots with 2-deep LDS pipeline ----
#pragma unroll
        for (int b = 0; b < 4; b++) {
            const ulonglong2* hp2 = (const ulonglong2*)(myhsm + b * 64);
            u64 aA0 = 0ull, aA1 = 0ull, aB0 = 0ull, aB1 = 0ull;
            ulonglong2 n0 = hp2[0], n1 = hp2[1];
#pragma unroll
            for (int j = 0; j < 8; j++) {
                ulonglong2 h2a = n0, h2b = n1;
                if (j < 7) { n0 = hp2[2 * j + 2]; n1 = hp2[2 * j + 3]; }
                aA0 = fma2(h2a.x, wA[4 * j + 0], aA0);
                aA1 = fma2(h2a.y, wA[4 * j + 1], aA1);
                aA0 = fma2(h2b.x, wA[4 * j + 2], aA0);
                aA1 = fma2(h2b.y, wA[4 * j + 3], aA1);
                aB0 = fma2(h2a.x, wB[4 * j + 0], aB0);
                aB1 = fma2(h2a.y, wB[4 * j + 1], aB1);
                aB0 = fma2(h2b.x, wB[4 * j + 2], aB0);
                aB1 = fma2(h2b.y, wB[4 * j + 3], aB1);
            }
            psum[p][ks * 288 + b * 72 + l]      = hsum(aA0) + hsum(aA1);
            psum[p][ks * 288 + b * 72 + l + 32] = hsum(aB0) + hsum(aB1);
        }
        __syncthreads();

        {
            float s = 0.f;
#pragma unroll
            for (int q = 0; q < 8; q++) s += psum[p][q * 288 + rb * 72 + rc];
            float val = tanhf(s + pv);
            g_hs[((size_t)t * Bb + bbase + rb) * Ee + obase + rc] = val;
            __syncwarp();
            if (l == 0 && t < Tt - 1) st_rel(myflag, (unsigned)(t + 1));
        }
    }
}

// ---------------- head GEMM: f32x2, 128x128 tile, 8x8 per thread ----------------
// A pre-packed {a,a} u64 in shared (no in-loop MOVs); B read as natural u64
// column pairs. Per kk per thread: 6 LDS.128 vs 32 fma2 -> FMA-pipe-bound at
// 2x the scalar floor.
__global__ void __launch_bounds__(256)
head_gemm_kernel(const float* __restrict__ w_head,
                 const float* __restrict__ b_head,
                 float* __restrict__ out) {
    __shared__ __align__(16) u64   As2p[16][128];   // 16 KB [k][row] packed {a,a}
    __shared__ __align__(16) float Bs[16][136];     // 8.5 KB [k][col], row stride 544B (16B mult)
    int tid = threadIdx.x;
    int rbase = blockIdx.x * 128;
    int cbase = blockIdx.y * 128;
    int ti = tid >> 4, tj = tid & 15;     // rows ti*8.., cols tj*8..
    int arow = tid >> 1, akq = (tid & 1) * 8;
    int bcol = tid >> 1, bkq = (tid & 1) * 8;

    u64 acc[8][4];
#pragma unroll
    for (int i = 0; i < 8; i++)
#pragma unroll
        for (int j = 0; j < 4; j++) acc[i][j] = 0ull;

    for (int k0 = 0; k0 < Ee; k0 += 16) {
        // A: 128 rows x 16 k, packed {a,a}, k-major
#pragma unroll
        for (int h = 0; h < 2; h++) {
            float4 av = *(const float4*)&g_hs[(size_t)(rbase + arow) * Ee + k0 + akq + h * 4];
            As2p[akq + h * 4 + 0][arow] = pack2(av.x);
            As2p[akq + h * 4 + 1][arow] = pack2(av.y);
            As2p[akq + h * 4 + 2][arow] = pack2(av.z);
            As2p[akq + h * 4 + 3][arow] = pack2(av.w);
        }
        // B: 128 cols x 16 k, transposed store
#pragma unroll
        for (int h = 0; h < 2; h++) {
            float4 bv = *(const float4*)&w_head[(size_t)(cbase + bcol) * Ee + k0 + bkq + h * 4];
            Bs[bkq + h * 4 + 0][bcol] = bv.x;
            Bs[bkq + h * 4 + 1][bcol] = bv.y;
            Bs[bkq + h * 4 + 2][bcol] = bv.z;
            Bs[bkq + h * 4 + 3][bcol] = bv.w;
        }
        __syncthreads();
#pragma unroll
        for (int kk = 0; kk < 16; kk++) {
            ulonglong2 aP0 = *(const ulonglong2*)&As2p[kk][ti * 8 + 0];   // rows 0,1
            ulonglong2 aP1 = *(const ulonglong2*)&As2p[kk][ti * 8 + 2];   // rows 2,3
            ulonglong2 aP2 = *(const ulonglong2*)&As2p[kk][ti * 8 + 4];   // rows 4,5
            ulonglong2 aP3 = *(const ulonglong2*)&As2p[kk][ti * 8 + 6];   // rows 6,7
            ulonglong2 bA = *(const ulonglong2*)&Bs[kk][tj * 8];          // cols 0-3
            ulonglong2 bB = *(const ulonglong2*)&Bs[kk][tj * 8 + 4];      // cols 4-7
            acc[0][0] = fma2(aP0.x, bA.x, acc[0][0]); acc[0][1] = fma2(aP0.x, bA.y, acc[0][1]);
            acc[0][2] = fma2(aP0.x, bB.x, acc[0][2]); acc[0][3] = fma2(aP0.x, bB.y, acc[0][3]);
            acc[1][0] = fma2(aP0.y, bA.x, acc[1][0]); acc[1][1] = fma2(aP0.y, bA.y, acc[1][1]);
            acc[1][2] = fma2(aP0.y, bB.x, acc[1][2]); acc[1][3] = fma2(aP0.y, bB.y, acc[1][3]);
            acc[2][0] = fma2(aP1.x, bA.x, acc[2][0]); acc[2][1] = fma2(aP1.x, bA.y, acc[2][1]);
            acc[2][2] = fma2(aP1.x, bB.x, acc[2][2]); acc[2][3] = fma2(aP1.x, bB.y, acc[2][3]);
            acc[3][0] = fma2(aP1.y, bA.x, acc[3][0]); acc[3][1] = fma2(aP1.y, bA.y, acc[3][1]);
            acc[3][2] = fma2(aP1.y, bB.x, acc[3][2]); acc[3][3] = fma2(aP1.y, bB.y, acc[3][3]);
            acc[4][0] = fma2(aP2.x, bA.x, acc[4][0]); acc[4][1] = fma2(aP2.x, bA.y, acc[4][1]);
            acc[4][2] = fma2(aP2.x, bB.x, acc[4][2]); acc[4][3] = fma2(aP2.x, bB.y, acc[4][3]);
            acc[5][0] = fma2(aP2.y, bA.x, acc[5][0]); acc[5][1] = fma2(aP2.y, bA.y, acc[5][1]);
            acc[5][2] = fma2(aP2.y, bB.x, acc[5][2]); acc[5][3] = fma2(aP2.y, bB.y, acc[5][3]);
            acc[6][0] = fma2(aP3.x, bA.x, acc[6][0]); acc[6][1] = fma2(aP3.x, bA.y, acc[6][1]);
            acc[6][2] = fma2(aP3.x, bB.x, acc[6][2]); acc[6][3] = fma2(aP3.x, bB.y, acc[6][3]);
            acc[7][0] = fma2(aP3.y, bA.x, acc[7][0]); acc[7][1] = fma2(aP3.y, bA.y, acc[7][1]);
            acc[7][2] = fma2(aP3.y, bB.x, acc[7][2]); acc[7][3] = fma2(aP3.y, bB.y, acc[7][3]);
        }
        __syncthreads();
    }
#pragma unroll
    for (int ii = 0; ii < 8; ii++) {
        int r  = rbase + ti * 8 + ii;      // r = t*B + b
        int bb = r & (Bb - 1);
        int tt = r >> 6;
        int cc = cbase + tj * 8;
        float* op = &out[(size_t)bb * (Tt * Vv) + (size_t)tt * Vv + cc];
        float4 o1, o2;
        o1.x = lo32(acc[ii][0]) + b_head[cc + 0];
        o1.y = hi32(acc[ii][0]) + b_head[cc + 1];
        o1.z = lo32(acc[ii][1]) + b_head[cc + 2];
        o1.w = hi32(acc[ii][1]) + b_head[cc + 3];
        o2.x = lo32(acc[ii][2]) + b_head[cc + 4];
        o2.y = hi32(acc[ii][2]) + b_head[cc + 5];
        o2.z = lo32(acc[ii][3]) + b_head[cc + 6];
        o2.w = hi32(acc[ii][3]) + b_head[cc + 7];
        *(float4*)op       = o1;
        *(float4*)(op + 4) = o2;
    }
}

// ---------------- launch ----------------
extern "C" void kernel_launch(void* const* d_in, const int* in_sizes, int n_in,
                              void* d_out, int out_size) {
    const int*   x      = (const int*)  d_in[0];
    const float* emb    = (const float*)d_in[1];
    const float* w_cell = (const float*)d_in[2];
    const float* b_cell = (const float*)d_in[3];
    const float* w_head = (const float*)d_in[4];
    const float* b_head = (const float*)d_in[5];
    const float* h0     = (const float*)d_in[6];
    float* out = (float*)d_out;

    zero_flag_kernel<<<128, 256>>>();
    p_gemm_kernel<<<dim3(Vv / 64, Ee / 64), 256>>>(emb, w_cell, b_cell);
    rnn_rec_kernel<<<128, 256>>>(x, w_cell, h0);
    head_gemm_kernel<<<dim3((Bb * Tt) / 128, Vv / 128), 256>>>(w_head, b_head, out);
}

// round 17
// speedup vs baseline: 1.0691x; 1.0691x over previous
#include <cuda_runtime.h>
#include <cstdint>

#define Bb   64
#define Tt   1024
#define Ee   512
#define Vv   256
#define NTILE 2048          // (Bb*Tt/128) * (Vv/64)

typedef unsigned long long u64;

// ---------------- device scratch ----------------
__device__ float    g_P[Vv * Ee];                  // P[v][o] = emb[v]·w_x[o] + b_cell[o]
__device__ float    g_hs[(size_t)Tt * Bb * Ee];    // hs[t][b][e]  (128 MB)
__device__ unsigned g_flag[128 * 8 * 32];          // per-CTA per-chunk flag, 128B stride
__device__ int      g_work;                        // head tile queue counter

// ---------------- packed f32x2 helpers ----------------
__device__ __forceinline__ u64 fma2(u64 a, u64 b, u64 c) {
    u64 d;
    asm("fma.rn.f32x2 %0, %1, %2, %3;" : "=l"(d) : "l"(a), "l"(b), "l"(c));
    return d;
}
__device__ __forceinline__ float lo32(u64 v) { return __uint_as_float((unsigned)(v & 0xffffffffull)); }
__device__ __forceinline__ float hi32(u64 v) { return __uint_as_float((unsigned)(v >> 32)); }
__device__ __forceinline__ float hsum(u64 v) { return lo32(v) + hi32(v); }
__device__ __forceinline__ void st_rel(unsigned* p, unsigned v) {
    asm volatile("st.release.gpu.global.u32 [%0], %1;" :: "l"(p), "r"(v) : "memory");
}
__device__ __forceinline__ unsigned ld_acq(const unsigned* p) {
    unsigned v;
    asm volatile("ld.acquire.gpu.global.u32 %0, [%1];" : "=r"(v) : "l"(p) : "memory");
    return v;
}

// ---------------- reset (each replay) ----------------
__global__ void zero_flag_kernel() {
    int i = blockIdx.x * 256 + threadIdx.x;
    g_flag[i] = 0u;
    if (i == 0) g_work = 0;
}

// ---------------- P = emb @ w_x^T + b_cell   (256 x 512, K=512) ----------------
__global__ void p_gemm_kernel(const float* __restrict__ emb,
                              const float* __restrict__ w_cell,
                              const float* __restrict__ b_cell) {
    __shared__ float As[64][16];
    __shared__ float Bs[16][64];
    int tid = threadIdx.x;
    int rbase = blockIdx.x * 64;   // v
    int cbase = blockIdx.y * 64;   // o
    int ti = tid >> 4, tj = tid & 15;
    int arow = tid >> 2, ac4 = (tid & 3) * 4;
    float acc[4][4] = {};

    for (int k0 = 0; k0 < Ee; k0 += 16) {
        float4 av = *(const float4*)&emb[(rbase + arow) * Ee + k0 + ac4];
        *(float4*)&As[arow][ac4] = av;
        float4 bv = *(const float4*)&w_cell[(size_t)(cbase + arow) * (2 * Ee) + k0 + ac4];
        Bs[ac4 + 0][arow] = bv.x; Bs[ac4 + 1][arow] = bv.y;
        Bs[ac4 + 2][arow] = bv.z; Bs[ac4 + 3][arow] = bv.w;
        __syncthreads();
#pragma unroll
        for (int kk = 0; kk < 16; kk++) {
            float a0 = As[ti * 4 + 0][kk];
            float a1 = As[ti * 4 + 1][kk];
            float a2 = As[ti * 4 + 2][kk];
            float a3 = As[ti * 4 + 3][kk];
            float4 b4 = *(const float4*)&Bs[kk][tj * 4];
            acc[0][0] = fmaf(a0, b4.x, acc[0][0]); acc[0][1] = fmaf(a0, b4.y, acc[0][1]);
            acc[0][2] = fmaf(a0, b4.z, acc[0][2]); acc[0][3] = fmaf(a0, b4.w, acc[0][3]);
            acc[1][0] = fmaf(a1, b4.x, acc[1][0]); acc[1][1] = fmaf(a1, b4.y, acc[1][1]);
            acc[1][2] = fmaf(a1, b4.z, acc[1][2]); acc[1][3] = fmaf(a1, b4.w, acc[1][3]);
            acc[2][0] = fmaf(a2, b4.x, acc[2][0]); acc[2][1] = fmaf(a2, b4.y, acc[2][1]);
            acc[2][2] = fmaf(a2, b4.z, acc[2][2]); acc[2][3] = fmaf(a2, b4.w, acc[2][3]);
            acc[3][0] = fmaf(a3, b4.x, acc[3][0]); acc[3][1] = fmaf(a3, b4.y, acc[3][1]);
            acc[3][2] = fmaf(a3, b4.z, acc[3][2]); acc[3][3] = fmaf(a3, b4.w, acc[3][3]);
        }
        __syncthreads();
    }
#pragma unroll
    for (int ii = 0; ii < 4; ii++) {
        int r = rbase + ti * 4 + ii;
        int c = cbase + tj * 4;
        float4 o;
        o.x = acc[ii][0] + b_cell[c + 0];
        o.y = acc[ii][1] + b_cell[c + 1];
        o.z = acc[ii][2] + b_cell[c + 2];
        o.w = acc[ii][3] + b_cell[c + 3];
        *(float4*)&g_P[r * Ee + c] = o;
    }
}

// ---------------- fused persistent kernel: rec (CTAs 0-127) + head work queue ----
__global__ void __launch_bounds__(256, 1)
rnn_fused_kernel(const int* __restrict__ x,
                 const float* __restrict__ w_cell,
                 const float* __restrict__ h0,
                 const float* __restrict__ w_head,
                 const float* __restrict__ b_head,
                 float* __restrict__ out) {
    // rec shared
    __shared__ __align__(16) float hsm[8 * 256];     // 8 KB
    __shared__ float psum[2][8 * 288];               // 2 x 9 KB
    // head shared
    __shared__ __align__(16) float As2[16][128];     // 8 KB   [k][row]
    __shared__ __align__(16) float Bs[16][68];       // 4.25 KB [k][col]
    __shared__ int s_idx, s_ready;

    int tid = threadIdx.x;
    int bid = blockIdx.x;

    // ================= recurrence (CTAs 0-127), R13-exact =================
    if (bid < 128) {
        int io  = bid & 7,  grp = bid >> 3;
        int obase = io * 64, bbase = grp * 4;
        int l  = tid & 31;
        int ks = tid >> 5;
        int k0 = ks * 64;

        u64 wA[32], wB[32];
        {
            const u64* wp = (const u64*)w_cell;
            int baseA = ((obase + l)      * (2 * Ee) + Ee + k0) >> 1;
            int baseB = ((obase + l + 32) * (2 * Ee) + Ee + k0) >> 1;
#pragma unroll
            for (int j = 0; j < 32; j++) wA[j] = wp[baseA + j];
#pragma unroll
            for (int j = 0; j < 32; j++) wB[j] = wp[baseB + j];
        }

        unsigned* myflag = &g_flag[(bid * 8 + ks) * 32];
        const unsigned* fA = &g_flag[((grp * 8 + ks) * 8 + ((l & 15) >> 1)) * 32];

        int rb = l >> 3, rc = ks * 8 + (l & 7);
        const int* xrow = x + (bbase + rb) * Tt;
        const float* prow_base = g_P + obase + rc;

        int bq0 = l >> 4, bq1 = (l + 32) >> 4;
        int kk  = (l & 15) * 4;

        float* myhsm = hsm + ks * 256;

        for (int t = 0; t < Tt; t++) {
            int p = t & 1;
            int   xv = __ldg(xrow + t);
            float pv = __ldg(&prow_base[xv * Ee]);

            if (t == 0) {
#pragma unroll
                for (int q = 0; q < 2; q++) {
                    int idx = l + 32 * q;
                    int kq  = (idx & 15) * 4;
                    *(float4*)&myhsm[(idx >> 4) * 64 + kq] = *(const float4*)&h0[k0 + kq];
                }
            } else {
                while (ld_acq(fA) < (unsigned)t) { }
                const float* base = g_hs + ((size_t)(t - 1) * Bb + bbase) * Ee + k0 + kk;
                float4 v0 = __ldcg((const float4*)(base + (size_t)bq0 * Ee));
                float4 v1 = __ldcg((const float4*)(base + (size_t)bq1 * Ee));
                *(float4*)&myhsm[bq0 * 64 + kk] = v0;
                *(float4*)&myhsm[bq1 * 64 + kk] = v1;
            }
            __syncwarp();

#pragma unroll
            for (int b = 0; b < 4; b++) {
                const ulonglong2* hp2 = (const ulonglong2*)(myhsm + b * 64);
                u64 aA0 = 0ull, aA1 = 0ull, aB0 = 0ull, aB1 = 0ull;
                ulonglong2 n0 = hp2[0], n1 = hp2[1];
#pragma unroll
                for (int j = 0; j < 8; j++) {
                    ulonglong2 h2a = n0, h2b = n1;
                    if (j < 7) { n0 = hp2[2 * j + 2]; n1 = hp2[2 * j + 3]; }
                    aA0 = fma2(h2a.x, wA[4 * j + 0], aA0);
                    aA1 = fma2(h2a.y, wA[4 * j + 1], aA1);
                    aA0 = fma2(h2b.x, wA[4 * j + 2], aA0);
                    aA1 = fma2(h2b.y, wA[4 * j + 3], aA1);
                    aB0 = fma2(h2a.x, wB[4 * j + 0], aB0);
                    aB1 = fma2(h2a.y, wB[4 * j + 1], aB1);
                    aB0 = fma2(h2b.x, wB[4 * j + 2], aB0);
                    aB1 = fma2(h2b.y, wB[4 * j + 3], aB1);
                }
                psum[p][ks * 288 + b * 72 + l]      = hsum(aA0) + hsum(aA1);
                psum[p][ks * 288 + b * 72 + l + 32] = hsum(aB0) + hsum(aB1);
            }
            __syncthreads();

            {
                float s = 0.f;
#pragma unroll
                for (int q = 0; q < 8; q++) s += psum[p][q * 288 + rb * 72 + rc];
                float val = tanhf(s + pv);
                g_hs[((size_t)t * Bb + bbase + rb) * Ee + obase + rc] = val;
                __syncwarp();
                if (l == 0) st_rel(myflag, (unsigned)(t + 1));   // release ALL t (1024 marks done)
            }
        }
    }

    // ================= head work queue (ALL CTAs) =================
    {
        int ti = tid >> 4, tj = tid & 15;
        int arow = tid >> 1, akq = (tid & 1) * 8;
        int bcol = tid >> 2, bkq = (tid & 3) * 4;

        for (;;) {
            if (tid == 0) s_idx = atomicAdd(&g_work, 1);
            __syncthreads();
            int idx = s_idx;
            __syncthreads();
            if (idx >= NTILE) break;

            int rbase = (idx >> 2) * 128;
            int cbase = (idx & 3) * 64;
            unsigned t_need = (unsigned)(((rbase + 127) >> 6) + 1);

            // readiness: all 1024 chunk flags >= t_need (acquire orders g_hs reads)
            for (;;) {
                bool ok = true;
                for (int i = tid; i < 1024; i += 256)
                    ok &= (ld_acq(&g_flag[i * 32]) >= t_need);
                if (tid == 0) s_ready = 1;
                __syncthreads();
                if (!ok) s_ready = 0;
                __syncthreads();
                if (s_ready) break;
            }

            // R13 head tile body
            float acc[8][4];
#pragma unroll
            for (int i = 0; i < 8; i++)
#pragma unroll
                for (int j = 0; j < 4; j++) acc[i][j] = 0.f;

            for (int k0 = 0; k0 < Ee; k0 += 16) {
#pragma unroll
                for (int h = 0; h < 2; h++) {
                    float4 av = *(const float4*)&g_hs[(size_t)(rbase + arow) * Ee + k0 + akq + h * 4];
                    As2[akq + h * 4 + 0][arow] = av.x;
                    As2[akq + h * 4 + 1][arow] = av.y;
                    As2[akq + h * 4 + 2][arow] = av.z;
                    As2[akq + h * 4 + 3][arow] = av.w;
                }
                {
                    float4 bv = *(const float4*)&w_head[(size_t)(cbase + bcol) * Ee + k0 + bkq];
                    Bs[bkq + 0][bcol] = bv.x; Bs[bkq + 1][bcol] = bv.y;
                    Bs[bkq + 2][bcol] = bv.z; Bs[bkq + 3][bcol] = bv.w;
                }
                __syncthreads();
#pragma unroll
                for (int kk = 0; kk < 16; kk++) {
                    float4 aL = *(const float4*)&As2[kk][ti * 8];
                    float4 aH = *(const float4*)&As2[kk][ti * 8 + 4];
                    float4 b4 = *(const float4*)&Bs[kk][tj * 4];
                    acc[0][0] = fmaf(aL.x, b4.x, acc[0][0]); acc[0][1] = fmaf(aL.x, b4.y, acc[0][1]);
                    acc[0][2] = fmaf(aL.x, b4.z, acc[0][2]); acc[0][3] = fmaf(aL.x, b4.w, acc[0][3]);
                    acc[1][0] = fmaf(aL.y, b4.x, acc[1][0]); acc[1][1] = fmaf(aL.y, b4.y, acc[1][1]);
                    acc[1][2] = fmaf(aL.y, b4.z, acc[1][2]); acc[1][3] = fmaf(aL.y, b4.w, acc[1][3]);
                    acc[2][0] = fmaf(aL.z, b4.x, acc[2][0]); acc[2][1] = fmaf(aL.z, b4.y, acc[2][1]);
                    acc[2][2] = fmaf(aL.z, b4.z, acc[2][2]); acc[2][3] = fmaf(aL.z, b4.w, acc[2][3]);
                    acc[3][0] = fmaf(aL.w, b4.x, acc[3][0]); acc[3][1] = fmaf(aL.w, b4.y, acc[3][1]);
                    acc[3][2] = fmaf(aL.w, b4.z, acc[3][2]); acc[3][3] = fmaf(aL.w, b4.w, acc[3][3]);
                    acc[4][0] = fmaf(aH.x, b4.x, acc[4][0]); acc[4][1] = fmaf(aH.x, b4.y, acc[4][1]);
                    acc[4][2] = fmaf(aH.x, b4.z, acc[4][2]); acc[4][3] = fmaf(aH.x, b4.w, acc[4][3]);
                    acc[5][0] = fmaf(aH.y, b4.x, acc[5][0]); acc[5][1] = fmaf(aH.y, b4.y, acc[5][1]);
                    acc[5][2] = fmaf(aH.y, b4.z, acc[5][2]); acc[5][3] = fmaf(aH.y, b4.w, acc[5][3]);
                    acc[6][0] = fmaf(aH.z, b4.x, acc[6][0]); acc[6][1] = fmaf(aH.z, b4.y, acc[6][1]);
                    acc[6][2] = fmaf(aH.z, b4.z, acc[6][2]); acc[6][3] = fmaf(aH.z, b4.w, acc[6][3]);
                    acc[7][0] = fmaf(aH.w, b4.x, acc[7][0]); acc[7][1] = fmaf(aH.w, b4.y, acc[7][1]);
                    acc[7][2] = fmaf(aH.w, b4.z, acc[7][2]); acc[7][3] = fmaf(aH.w, b4.w, acc[7][3]);
                }
                __syncthreads();
            }
#pragma unroll
            for (int ii = 0; ii < 8; ii++) {
                int r  = rbase + ti * 8 + ii;      // r = t*B + b
                int bb = r & (Bb - 1);
                int tt = r >> 6;
                int cc = cbase + tj * 4;
                float4 o;
                o.x = acc[ii][0] + b_head[cc + 0];
                o.y = acc[ii][1] + b_head[cc + 1];
                o.z = acc[ii][2] + b_head[cc + 2];
                o.w = acc[ii][3] + b_head[cc + 3];
                *(float4*)&out[(size_t)bb * (Tt * Vv) + (size_t)tt * Vv + cc] = o;
            }
        }
    }
}

// ---------------- launch ----------------
extern "C" void kernel_launch(void* const* d_in, const int* in_sizes, int n_in,
                              void* d_out, int out_size) {
    const int*   x      = (const int*)  d_in[0];
    const float* emb    = (const float*)d_in[1];
    const float* w_cell = (const float*)d_in[2];
    const float* b_cell = (const float*)d_in[3];
    const float* w_head = (const float*)d_in[4];
    const float* b_head = (const float*)d_in[5];
    const float* h0     = (const float*)d_in[6];
    float* out = (float*)d_out;

    zero_flag_kernel<<<128, 256>>>();
    p_gemm_kernel<<<dim3(Vv / 64, Ee / 64), 256>>>(emb, w_cell, b_cell);
    rnn_fused_kernel<<<148, 256>>>(x, w_cell, h0, w_head, b_head, out);
}